// round 11
// baseline (speedup 1.0000x reference)
#include <cuda_runtime.h>
#include <cstdint>
#include <math.h>

#define SEQ   2048
#define BATCH 64
#define INP   256
#define HID   256

typedef unsigned long long ull;

// ---------- packed f32x2 helpers (Blackwell FFMA2 path, PTX-only) ----------
__device__ __forceinline__ void ffma2(ull& d, ull a, ull b) {
    asm("fma.rn.f32x2 %0, %1, %2, %0;" : "+l"(d) : "l"(a), "l"(b));
}
__device__ __forceinline__ ull pk(float a, float b) {
    ull r; asm("mov.b64 %0, {%1, %2};" : "=l"(r) : "f"(a), "f"(b)); return r;
}
__device__ __forceinline__ ull pku(unsigned a, unsigned b) {
    ull r; asm("mov.b64 %0, {%1, %2};" : "=l"(r) : "r"(a), "r"(b)); return r;
}
__device__ __forceinline__ float2 unpk(ull v) {
    float x, y; asm("mov.b64 {%0, %1}, %2;" : "=f"(x), "=f"(y) : "l"(v));
    return make_float2(x, y);
}
__device__ __forceinline__ unsigned smem_u32(const void* p) {
    unsigned a;
    asm("{ .reg .u64 t; cvta.to.shared.u64 t, %1; cvt.u32.u64 %0, t; }"
        : "=r"(a) : "l"(p));
    return a;
}
__device__ __forceinline__ unsigned mapa_peer(unsigned local_addr, unsigned peer) {
    unsigned r;
    asm("mapa.shared::cluster.u32 %0, %1, %2;" : "=r"(r) : "r"(local_addr), "r"(peer));
    return r;
}
// Branch-free tanh: 1 - 2/(e^{2x}+1). ex2/rcp approx, abs err ~1e-7.
__device__ __forceinline__ float fast_tanh(float x) {
    float e;
    asm("ex2.approx.ftz.f32 %0, %1;" : "=f"(e) : "f"(x * 2.8853900817779268f));
    float r;
    asm("rcp.approx.ftz.f32 %0, %1;" : "=f"(r) : "f"(e + 1.0f));
    return fmaf(-2.0f, r, 1.0f);
}

// =====================================================================
// Phase 1: xp[t,b,h] = x[t,b]·W_ih[h] + b_ih[h] + b_hh[h]  (unchanged)
// =====================================================================
__global__ __launch_bounds__(256) void xp_gemm_kernel(
    const float* __restrict__ x,
    const float* __restrict__ Wih,
    const float* __restrict__ bih,
    const float* __restrict__ bhh,
    float* __restrict__ out)
{
    __shared__ float Xs[32][68];
    __shared__ float Ws[32][257];

    const int t   = blockIdx.x;
    const int tid = threadIdx.x;
    const int tn  = tid & 31;
    const int tm  = tid >> 5;
    const int m0  = tm * 8;

    const float* xt = x + (size_t)t * BATCH * INP;

    ull acc[8][4];
    #pragma unroll
    for (int u = 0; u < 8; ++u)
        #pragma unroll
        for (int v = 0; v < 4; ++v) acc[u][v] = 0ull;

    for (int kc = 0; kc < INP; kc += 32) {
        #pragma unroll
        for (int r = 0; r < 2; ++r) {
            int idx = tid + 256 * r;
            int m   = idx >> 3;
            int k4  = (idx & 7) * 4;
            float4 v = *(const float4*)(xt + (size_t)m * INP + kc + k4);
            Xs[k4 + 0][m] = v.x; Xs[k4 + 1][m] = v.y;
            Xs[k4 + 2][m] = v.z; Xs[k4 + 3][m] = v.w;
        }
        #pragma unroll
        for (int r = 0; r < 8; ++r) {
            int idx = tid + 256 * r;
            int h   = idx >> 3;
            int k4  = (idx & 7) * 4;
            float4 v = *(const float4*)(Wih + (size_t)h * INP + kc + k4);
            Ws[k4 + 0][h] = v.x; Ws[k4 + 1][h] = v.y;
            Ws[k4 + 2][h] = v.z; Ws[k4 + 3][h] = v.w;
        }
        __syncthreads();

        #pragma unroll
        for (int k = 0; k < 32; ++k) {
            float4 a0 = *(const float4*)&Xs[k][m0];
            float4 a1 = *(const float4*)&Xs[k][m0 + 4];
            ull ap[8];
            ap[0] = pk(a0.x, a0.x); ap[1] = pk(a0.y, a0.y);
            ap[2] = pk(a0.z, a0.z); ap[3] = pk(a0.w, a0.w);
            ap[4] = pk(a1.x, a1.x); ap[5] = pk(a1.y, a1.y);
            ap[6] = pk(a1.z, a1.z); ap[7] = pk(a1.w, a1.w);

            float w[8];
            #pragma unroll
            for (int v = 0; v < 8; ++v) w[v] = Ws[k][tn + 32 * v];

            #pragma unroll
            for (int v2 = 0; v2 < 4; ++v2) {
                ull wp = pk(w[2 * v2], w[2 * v2 + 1]);
                #pragma unroll
                for (int u = 0; u < 8; ++u)
                    ffma2(acc[u][v2], wp, ap[u]);
            }
        }
        __syncthreads();
    }

    float ba[4], bb[4];
    #pragma unroll
    for (int v2 = 0; v2 < 4; ++v2) {
        int hA = tn + 64 * v2, hB = hA + 32;
        ba[v2] = bih[hA] + bhh[hA];
        bb[v2] = bih[hB] + bhh[hB];
    }
    float* ot = out + (size_t)t * BATCH * HID;
    #pragma unroll
    for (int u = 0; u < 8; ++u) {
        float* row = ot + (size_t)(m0 + u) * HID;
        #pragma unroll
        for (int v2 = 0; v2 < 4; ++v2) {
            float2 s = unpk(acc[u][v2]);
            row[tn + 64 * v2]      = s.x + ba[v2];
            row[tn + 64 * v2 + 32] = s.y + bb[v2];
        }
    }
}

// =====================================================================
// Phase 2: serial scan, v9 — R8 structure x TWO batches per cluster.
// grid = 64 CTAs (32 clusters of 2). Cluster c handles batches 2c,2c+1;
// rank r finalizes rows [128r,+128) of both, over all 256 k.
// 512 threads: jj=tid&127 (row), g=tid>>7 (k-window):
//   g0/g1: local k — compute immediately, no waiting (g0 finalizes)
//   g2/g3: peer  k — poll batch A pairs, matvec A (B's transit
//          completes underneath), poll B (≈instant), matvec B.
// Same W registers serve both batches (W is batch-independent).
// Remote h as {f32,seq} u64 pairs (single-copy atomic, seq validates;
// no fences/mbarriers). Local h plain smem ordered by the two BARs.
// =====================================================================
__global__ __launch_bounds__(512, 1) __cluster_dims__(2, 1, 1)
void rnn_scan_kernel(
    const float* __restrict__ Whh,  // [HID][HID]
    float* __restrict__ out)        // in: xp, out: h   [SEQ][BATCH][HID]
{
    __shared__ float hbuf[2][2][128];               // [batch][parity][jj]
    __shared__ alignas(16) ull prbuf[2][2][128];    // [batch][parity][idx] peer pairs
    __shared__ float pbuf[2][512];                  // [batch][4*jj+g] partials

    const int bidx = blockIdx.x;
    const int r    = bidx & 1;             // cluster rank
    const int bA   = (bidx >> 1) * 2;      // batch A (B = bA+1)
    const int tid  = threadIdx.x;
    const int jj   = tid & 127;            // row within my half
    const int g    = tid >> 7;             // k-window group
    const int lane = tid & 31;
    const int j    = 128 * r + jj;         // global row

    const int koff = (g < 2) ? (128 * r + 64 * g)
                             : (128 * (1 - r) + 64 * (g - 2));

    // ---- register-resident W: W_hh[j][koff + 0..63] (shared by A & B) ----
    ull wreg[32];
    {
        const float* wrow = Whh + (size_t)j * HID + koff;
        #pragma unroll
        for (int p = 0; p < 32; ++p)
            wreg[p] = *(const ull*)(wrow + 2 * p);
    }

    // ---- init smem ----
    ((float*)hbuf)[tid] = 0.f;                // 512 floats
    ((ull*)prbuf)[tid] = 0ull;                // 512 pairs: val=0, seq=0
    __syncthreads();
    asm volatile("barrier.cluster.arrive.aligned;" ::: "memory");
    asm volatile("barrier.cluster.wait.aligned;"   ::: "memory");

    const unsigned peer      = (unsigned)(r ^ 1);
    const unsigned prbuf_l   = smem_u32(prbuf);
    const unsigned peer_pr   = mapa_peer(prbuf_l, peer);

    const size_t stride = (size_t)BATCH * HID;
    float* colA = out + (size_t)bA * HID + j;
    float* colB = colA + HID;               // batch bA+1

    // xp prefetch queues, depth 2 (g0 only)
    float xA0 = 0.f, xA1 = 0.f, xB0 = 0.f, xB1 = 0.f;
    if (g == 0) {
        xA0 = __ldcg(colA);           xB0 = __ldcg(colB);
        xA1 = __ldcg(colA + stride);  xB1 = __ldcg(colB + stride);
    }

    // my remote publish slot on peer: idx == jj (peer window (jj<64?0:1))
    const unsigned rsloff = (unsigned)jj * 8u;

    for (int t = 0; t < SEQ; ++t) {
        const unsigned sp = (unsigned)(t & 1);   // publish parity
        const unsigned rp = sp ^ 1u;             // read parity

        float partA, partB;

        if (g < 2) {
            // ---- local-k matvec for A then B (zero waiting) ----
            {
                const ulonglong2* h2 =
                    (const ulonglong2*)&hbuf[0][rp][64 * g];
                ull a0 = 0ull, a1 = 0ull;
                #pragma unroll
                for (int q = 0; q < 16; ++q) {
                    ulonglong2 h = h2[q];
                    ffma2(a0, wreg[2 * q],     h.x);
                    ffma2(a1, wreg[2 * q + 1], h.y);
                }
                float2 s0 = unpk(a0), s1 = unpk(a1);
                partA = (s0.x + s0.y) + (s1.x + s1.y);
            }
            {
                const ulonglong2* h2 =
                    (const ulonglong2*)&hbuf[1][rp][64 * g];
                ull a0 = 0ull, a1 = 0ull;
                #pragma unroll
                for (int q = 0; q < 16; ++q) {
                    ulonglong2 h = h2[q];
                    ffma2(a0, wreg[2 * q],     h.x);
                    ffma2(a1, wreg[2 * q + 1], h.y);
                }
                float2 s0 = unpk(a0), s1 = unpk(a1);
                partB = (s0.x + s0.y) + (s1.x + s1.y);
            }
        } else {
            // ---- remote-k: poll A, matvec A (B arrives under it), poll B ----
            const int win = g - 2;               // my window: idx 64*win..+63
            const unsigned T = (unsigned)t;

            #pragma unroll
            for (int bb2 = 0; bb2 < 2; ++bb2) {
                // poll 64 slots of my window, 2 per lane
                const unsigned base = prbuf_l
                    + (unsigned)bb2 * 2048u + rp * 1024u
                    + (unsigned)win * 512u;
                const unsigned aA = base + (unsigned)lane * 8u;
                const unsigned aB = aA + 256u;
                unsigned ok;
                do {
                    ull v0, v1;
                    asm volatile("ld.volatile.shared.u64 %0, [%1];"
                                 : "=l"(v0) : "r"(aA) : "memory");
                    asm volatile("ld.volatile.shared.u64 %0, [%1];"
                                 : "=l"(v1) : "r"(aB) : "memory");
                    ok = ((unsigned)(v0 >> 32) == T)
                       & ((unsigned)(v1 >> 32) == T);
                } while (__all_sync(0xFFFFFFFFu, ok) == 0);

                // matvec from pairs (broadcast reads)
                const uint4* pq = (const uint4*)((const char*)prbuf
                                   + bb2 * 2048 + (int)rp * 1024 + win * 512);
                ull a0 = 0ull, a1 = 0ull;
                #pragma unroll
                for (int q = 0; q < 16; ++q) {
                    uint4 vA = pq[2 * q];        // {h0,s0,h1,s1}
                    uint4 vB = pq[2 * q + 1];
                    ffma2(a0, wreg[2 * q],     pku(vA.x, vA.z));
                    ffma2(a1, wreg[2 * q + 1], pku(vB.x, vB.z));
                }
                float2 s0 = unpk(a0), s1 = unpk(a1);
                float pr = (s0.x + s0.y) + (s1.x + s1.y);
                if (bb2 == 0) partA = pr; else partB = pr;
            }
        }

        pbuf[0][4 * jj + g] = partA;
        pbuf[1][4 * jj + g] = partB;

        __syncthreads();   // BAR1: partials visible

        if (g == 0) {
            float4 pA = *(const float4*)&pbuf[0][4 * jj];
            float4 pB = *(const float4*)&pbuf[1][4 * jj];
            float valA = fast_tanh(xA0 + ((pA.x + pA.y) + (pA.z + pA.w)));
            float valB = fast_tanh(xB0 + ((pB.x + pB.y) + (pB.z + pB.w)));

            // remote pair sends FIRST (start both transits early)
            if (t + 1 < SEQ) {
                ull hvA = pku(__float_as_uint(valA), (unsigned)(t + 1));
                ull hvB = pku(__float_as_uint(valB), (unsigned)(t + 1));
                asm volatile("st.shared::cluster.u64 [%0], %1;"
                             :: "r"(peer_pr + sp * 1024u + rsloff),
                                "l"(hvA) : "memory");
                asm volatile("st.shared::cluster.u64 [%0], %1;"
                             :: "r"(peer_pr + 2048u + sp * 1024u + rsloff),
                                "l"(hvB) : "memory");
            }
            // local h (ordered by BAR2)
            hbuf[0][sp][jj] = valA;
            hbuf[1][sp][jj] = valB;
            // outputs
            colA[(size_t)t * stride] = valA;
            colB[(size_t)t * stride] = valB;
            // advance xp queues
            xA0 = xA1; xB0 = xB1;
            if (t + 2 < SEQ) {
                xA1 = __ldcg(colA + (size_t)(t + 2) * stride);
                xB1 = __ldcg(colB + (size_t)(t + 2) * stride);
            }
        }

        __syncthreads();   // BAR2: h/pbuf safe for next step
    }

    asm volatile("barrier.cluster.arrive.aligned;" ::: "memory");
    asm volatile("barrier.cluster.wait.aligned;"   ::: "memory");
}

// =====================================================================
extern "C" void kernel_launch(void* const* d_in, const int* in_sizes, int n_in,
                              void* d_out, int out_size) {
    const float* x   = (const float*)d_in[0];  // [SEQ][BATCH][INP]
    const float* Wih = (const float*)d_in[1];  // [HID][INP]
    const float* Whh = (const float*)d_in[2];  // [HID][HID]
    const float* bih = (const float*)d_in[3];  // [HID]
    const float* bhh = (const float*)d_in[4];  // [HID]
    float* out = (float*)d_out;                // [SEQ][BATCH][HID]

    xp_gemm_kernel<<<SEQ, 256>>>(x, Wih, bih, bhh, out);
    rnn_scan_kernel<<<BATCH, 512>>>(Whh, out);
}

// round 12
// speedup vs baseline: 1.1411x; 1.1411x over previous
#include <cuda_runtime.h>
#include <cstdint>
#include <math.h>

#define SEQ   2048
#define BATCH 64
#define INP   256
#define HID   256

typedef unsigned long long ull;

// ---------- packed f32x2 helpers (Blackwell FFMA2 path, PTX-only) ----------
__device__ __forceinline__ void ffma2(ull& d, ull a, ull b) {
    asm("fma.rn.f32x2 %0, %1, %2, %0;" : "+l"(d) : "l"(a), "l"(b));
}
__device__ __forceinline__ ull pk(float a, float b) {
    ull r; asm("mov.b64 %0, {%1, %2};" : "=l"(r) : "f"(a), "f"(b)); return r;
}
__device__ __forceinline__ ull pku(unsigned a, unsigned b) {
    ull r; asm("mov.b64 %0, {%1, %2};" : "=l"(r) : "r"(a), "r"(b)); return r;
}
__device__ __forceinline__ float2 unpk(ull v) {
    float x, y; asm("mov.b64 {%0, %1}, %2;" : "=f"(x), "=f"(y) : "l"(v));
    return make_float2(x, y);
}
__device__ __forceinline__ unsigned smem_u32(const void* p) {
    unsigned a;
    asm("{ .reg .u64 t; cvta.to.shared.u64 t, %1; cvt.u32.u64 %0, t; }"
        : "=r"(a) : "l"(p));
    return a;
}
__device__ __forceinline__ unsigned mapa_peer(unsigned local_addr, unsigned peer) {
    unsigned r;
    asm("mapa.shared::cluster.u32 %0, %1, %2;" : "=r"(r) : "r"(local_addr), "r"(peer));
    return r;
}
// Branch-free tanh: 1 - 2/(e^{2x}+1). ex2/rcp approx, abs err ~1e-7.
__device__ __forceinline__ float fast_tanh(float x) {
    float e;
    asm("ex2.approx.ftz.f32 %0, %1;" : "=f"(e) : "f"(x * 2.8853900817779268f));
    float r;
    asm("rcp.approx.ftz.f32 %0, %1;" : "=f"(r) : "f"(e + 1.0f));
    return fmaf(-2.0f, r, 1.0f);
}

// =====================================================================
// Phase 1: xp[t,b,h] = x[t,b]·W_ih[h] + b_ih[h] + b_hh[h]  (unchanged)
// =====================================================================
__global__ __launch_bounds__(256) void xp_gemm_kernel(
    const float* __restrict__ x,
    const float* __restrict__ Wih,
    const float* __restrict__ bih,
    const float* __restrict__ bhh,
    float* __restrict__ out)
{
    __shared__ float Xs[32][68];
    __shared__ float Ws[32][257];

    const int t   = blockIdx.x;
    const int tid = threadIdx.x;
    const int tn  = tid & 31;
    const int tm  = tid >> 5;
    const int m0  = tm * 8;

    const float* xt = x + (size_t)t * BATCH * INP;

    ull acc[8][4];
    #pragma unroll
    for (int u = 0; u < 8; ++u)
        #pragma unroll
        for (int v = 0; v < 4; ++v) acc[u][v] = 0ull;

    for (int kc = 0; kc < INP; kc += 32) {
        #pragma unroll
        for (int r = 0; r < 2; ++r) {
            int idx = tid + 256 * r;
            int m   = idx >> 3;
            int k4  = (idx & 7) * 4;
            float4 v = *(const float4*)(xt + (size_t)m * INP + kc + k4);
            Xs[k4 + 0][m] = v.x; Xs[k4 + 1][m] = v.y;
            Xs[k4 + 2][m] = v.z; Xs[k4 + 3][m] = v.w;
        }
        #pragma unroll
        for (int r = 0; r < 8; ++r) {
            int idx = tid + 256 * r;
            int h   = idx >> 3;
            int k4  = (idx & 7) * 4;
            float4 v = *(const float4*)(Wih + (size_t)h * INP + kc + k4);
            Ws[k4 + 0][h] = v.x; Ws[k4 + 1][h] = v.y;
            Ws[k4 + 2][h] = v.z; Ws[k4 + 3][h] = v.w;
        }
        __syncthreads();

        #pragma unroll
        for (int k = 0; k < 32; ++k) {
            float4 a0 = *(const float4*)&Xs[k][m0];
            float4 a1 = *(const float4*)&Xs[k][m0 + 4];
            ull ap[8];
            ap[0] = pk(a0.x, a0.x); ap[1] = pk(a0.y, a0.y);
            ap[2] = pk(a0.z, a0.z); ap[3] = pk(a0.w, a0.w);
            ap[4] = pk(a1.x, a1.x); ap[5] = pk(a1.y, a1.y);
            ap[6] = pk(a1.z, a1.z); ap[7] = pk(a1.w, a1.w);

            float w[8];
            #pragma unroll
            for (int v = 0; v < 8; ++v) w[v] = Ws[k][tn + 32 * v];

            #pragma unroll
            for (int v2 = 0; v2 < 4; ++v2) {
                ull wp = pk(w[2 * v2], w[2 * v2 + 1]);
                #pragma unroll
                for (int u = 0; u < 8; ++u)
                    ffma2(acc[u][v2], wp, ap[u]);
            }
        }
        __syncthreads();
    }

    float ba[4], bb[4];
    #pragma unroll
    for (int v2 = 0; v2 < 4; ++v2) {
        int hA = tn + 64 * v2, hB = hA + 32;
        ba[v2] = bih[hA] + bhh[hA];
        bb[v2] = bih[hB] + bhh[hB];
    }
    float* ot = out + (size_t)t * BATCH * HID;
    #pragma unroll
    for (int u = 0; u < 8; ++u) {
        float* row = ot + (size_t)(m0 + u) * HID;
        #pragma unroll
        for (int v2 = 0; v2 < 4; ++v2) {
            float2 s = unpk(acc[u][v2]);
            row[tn + 64 * v2]      = s.x + ba[v2];
            row[tn + 64 * v2 + 32] = s.y + bb[v2];
        }
    }
}

// =====================================================================
// Phase 2: serial scan, v10 — warp-fused rows, per-lane local+remote k.
// grid = 128 (cluster 2); rank r finalizes rows [128r,+128), all 256 k.
// Warp w: rows 8w..8w+7. Lane l: quad=l>>2 -> row jj=8w+quad, g=l&3:
//   local  k: [128r     + 32g, +32)  (h from smem, computed FIRST —
//                                     overlaps inbound DSMEM transit)
//   remote k: [128(1-r) + 32g, +32)  (h from {f32,seq} u64 pairs)
// Quad partials combine via 2x shfl_xor; every warp finalizes its own
// 8 rows and sends their h pairs immediately (no cross-warp wait on
// the send path). ONE bar.sync per step (orders local h).
// Padded layouts: hl window stride 36 floats, pair window stride 34 —
// quad-strided LDS.128 addresses land in disjoint banks.
// =====================================================================
#define HLS  36                    // hl window stride (floats)
#define PRS  34                    // pair window stride (ull)

__global__ __launch_bounds__(512, 1) __cluster_dims__(2, 1, 1)
void rnn_scan_kernel(
    const float* __restrict__ Whh,  // [HID][HID]
    float* __restrict__ out)        // in: xp, out: h   [SEQ][BATCH][HID]
{
    __shared__ float hl[2][4 * HLS];              // local h, padded windows
    __shared__ alignas(16) ull prbuf[2][4 * PRS]; // remote h pairs, padded

    const int bidx = blockIdx.x;
    const int b    = bidx >> 1;
    const int r    = bidx & 1;             // cluster rank
    const int tid  = threadIdx.x;
    const int l    = tid & 31;
    const int w    = tid >> 5;
    const int jj   = 8 * w + (l >> 2);     // my row within half
    const int g    = l & 3;                // k-window (32 wide)
    const int j    = 128 * r + jj;         // global row

    // ---- register-resident W: 16 local + 16 remote ull pairs ----
    ull wl[16], wr[16];
    {
        const float* wrow = Whh + (size_t)j * HID;
        const float* pl = wrow + 128 * r       + 32 * g;
        const float* pr = wrow + 128 * (1 - r) + 32 * g;
        #pragma unroll
        for (int p = 0; p < 16; ++p) {
            wl[p] = *(const ull*)(pl + 2 * p);
            wr[p] = *(const ull*)(pr + 2 * p);
        }
    }

    // padded offsets
    const int hl_off = HLS * (jj >> 5) + (jj & 31);        // my row in hl
    const int pr_off = PRS * (jj >> 5) + (jj & 31);        // my row in peer prbuf

    // ---- init smem ----
    for (int i = tid; i < 2 * 4 * HLS; i += 512) ((float*)hl)[i] = 0.f;
    for (int i = tid; i < 2 * 4 * PRS; i += 512) ((ull*)prbuf)[i] = 0ull;
    __syncthreads();
    asm volatile("barrier.cluster.arrive.aligned;" ::: "memory");
    asm volatile("barrier.cluster.wait.aligned;"   ::: "memory");

    const unsigned peer    = (unsigned)(r ^ 1);
    const unsigned pr_l    = smem_u32(prbuf);
    const unsigned peer_pr = mapa_peer(pr_l, peer);

    const size_t stride = (size_t)BATCH * HID;
    float* col = out + (size_t)b * HID + j;

    // xp queue depth 2 (all lanes; quad-broadcast address)
    float xq0 = __ldcg(col);
    float xq1 = __ldcg(col + stride);

    // poll addresses: lane validates slots l, l+32, l+64, l+96
    // (padded offsets l + PRS*c -> lane-consecutive, conflict-free)
    for (int t = 0; t < SEQ; ++t) {
        const unsigned sp = (unsigned)(t & 1);   // publish parity
        const unsigned rp = sp ^ 1u;             // read parity

        // ---- 1) LOCAL matvec first (overlaps inbound transit) ----
        ull a0 = 0ull, a1 = 0ull;
        {
            const float4* h4 = (const float4*)&hl[rp][HLS * g];
            #pragma unroll
            for (int q = 0; q < 8; ++q) {
                float4 v = h4[q];
                ffma2(a0, wl[2 * q],     pk(v.x, v.y));
                ffma2(a1, wl[2 * q + 1], pk(v.z, v.w));
            }
        }

        // ---- 2) collective poll of the 128 remote slots ----
        {
            const unsigned base = pr_l + rp * (4 * PRS * 8u);
            const unsigned aA = base + (unsigned)l * 8u;
            const unsigned aB = aA + PRS * 8u;
            const unsigned aC = aB + PRS * 8u;
            const unsigned aD = aC + PRS * 8u;
            const unsigned T  = (unsigned)t;
            unsigned ok;
            do {
                ull v0, v1, v2, v3;
                asm volatile("ld.volatile.shared.u64 %0, [%1];"
                             : "=l"(v0) : "r"(aA) : "memory");
                asm volatile("ld.volatile.shared.u64 %0, [%1];"
                             : "=l"(v1) : "r"(aB) : "memory");
                asm volatile("ld.volatile.shared.u64 %0, [%1];"
                             : "=l"(v2) : "r"(aC) : "memory");
                asm volatile("ld.volatile.shared.u64 %0, [%1];"
                             : "=l"(v3) : "r"(aD) : "memory");
                ok = ((unsigned)(v0 >> 32) == T) & ((unsigned)(v1 >> 32) == T)
                   & ((unsigned)(v2 >> 32) == T) & ((unsigned)(v3 >> 32) == T);
            } while (__all_sync(0xFFFFFFFFu, ok) == 0);
        }

        // ---- 3) REMOTE matvec from validated pairs ----
        ull a2 = 0ull, a3 = 0ull;
        {
            const uint4* pq = (const uint4*)&prbuf[rp][PRS * g];
            #pragma unroll
            for (int q = 0; q < 8; ++q) {
                uint4 vA = pq[2 * q];        // pairs {h,s}{h,s}
                uint4 vB = pq[2 * q + 1];
                ffma2(a2, wr[2 * q],     pku(vA.x, vA.z));
                ffma2(a3, wr[2 * q + 1], pku(vB.x, vB.z));
            }
        }

        // ---- 4) combine quad partials, finalize ----
        float2 s0 = unpk(a0), s1 = unpk(a1), s2 = unpk(a2), s3 = unpk(a3);
        float part = ((s0.x + s0.y) + (s1.x + s1.y))
                   + ((s2.x + s2.y) + (s3.x + s3.y));
        part += __shfl_xor_sync(0xFFFFFFFFu, part, 1);
        part += __shfl_xor_sync(0xFFFFFFFFu, part, 2);

        float val = fast_tanh(xq0 + part);   // all 4 lanes, branchless

        if (g == 0) {
            // remote send FIRST — per-warp, before any barrier
            if (t + 1 < SEQ) {
                ull hv = pku(__float_as_uint(val), (unsigned)(t + 1));
                asm volatile("st.shared::cluster.u64 [%0], %1;"
                             :: "r"(peer_pr + sp * (4 * PRS * 8u)
                                            + (unsigned)pr_off * 8u),
                                "l"(hv) : "memory");
            }
            hl[sp][hl_off] = val;            // local h (ordered by BAR)
            col[(size_t)t * stride] = val;   // h_t -> gmem
        }

        // advance xp queue
        xq0 = xq1;
        if (t + 2 < SEQ) xq1 = __ldcg(col + (size_t)(t + 2) * stride);

        __syncthreads();   // the single per-step barrier
    }

    asm volatile("barrier.cluster.arrive.aligned;" ::: "memory");
    asm volatile("barrier.cluster.wait.aligned;"   ::: "memory");
}

// =====================================================================
extern "C" void kernel_launch(void* const* d_in, const int* in_sizes, int n_in,
                              void* d_out, int out_size) {
    const float* x   = (const float*)d_in[0];  // [SEQ][BATCH][INP]
    const float* Wih = (const float*)d_in[1];  // [HID][INP]
    const float* Whh = (const float*)d_in[2];  // [HID][HID]
    const float* bih = (const float*)d_in[3];  // [HID]
    const float* bhh = (const float*)d_in[4];  // [HID]
    float* out = (float*)d_out;                // [SEQ][BATCH][HID]

    xp_gemm_kernel<<<SEQ, 256>>>(x, Wih, bih, bhh, out);
    rnn_scan_kernel<<<2 * BATCH, 512>>>(Whh, out);
}